// round 10
// baseline (speedup 1.0000x reference)
#include <cuda_runtime.h>
#include <cstdint>

// Problem shape (fixed by the dataset)
#define B  8
#define T  4096
#define D  1024
#define V4D 256                     // float4 per row
#define SLICES 64                   // 16-float D-slices
#define SLICE_V4 4                  // 4 float4 per slice
#define TILE 256                    // rows per tile iteration
#define QN   64                     // row-blocks per tile (TILE/RPT)
#define RPT  4                      // rows per thread per tile
#define THREADS 256                 // 64 q-blocks x 4 columns
#define ITERS (T / TILE)            // 16
#define NCTAS (B * SLICES)          // 512
#define TILE_STRIDE (TILE * V4D)    // float4 elements per tile step

// exact gelu via erff (polynomial path, no MUFU exp):
// jax.nn.gelu(approximate=False) = 0.5*x*(1+erf(x/sqrt(2)))
__device__ __forceinline__ float gelu_exact(float x) {
    return 0.5f * x * (1.0f + erff(x * 0.7071067811865476f));
}

// lengths dtype sniffing: reference asks for int64 but JAX default config
// (x64 disabled) emits int32. Reading the first 8 int32 words is safe under
// BOTH layouts. If genuine int64, every odd 32-bit word is the zero
// high-half (lengths < 4096). If int32, odd words are random lengths.
__device__ __forceinline__ int load_length(const void* lp, int b) {
    const int* p32 = (const int*)lp;
    bool is64 = (p32[1] == 0) & (p32[3] == 0) & (p32[5] == 0) & (p32[7] == 0);
    if (is64) return (int)((const long long*)lp)[b];
    return p32[b];
}

__global__ void __launch_bounds__(THREADS, 4)
fused_kernel(const float* __restrict__ x,
             const void* __restrict__ lengths,
             float* __restrict__ out) {
    // only scan state in smem (c stays in registers), double-buffered
    __shared__ float4 part[2][QN * 5];            // stride 5: conflict-free
    __shared__ float4 htot[2][2][SLICE_V4];       // half-column totals

    const int tid  = threadIdx.x;
    const int q    = tid >> 2;      // row-block index  [0,64)
    const int l    = tid & 3;       // float4 column    [0,4)
    const int lane = tid & 31;
    const int w    = tid >> 5;      // warp id [0,8)
    const int cw   = w & 3;         // scan column of this warp
    const int hh   = w >> 2;        // scan half of this warp

    const int s = blockIdx.x & (SLICES - 1);
    const int b = blockIdx.x >> 6;
    const int len = load_length(lengths, b);
    const int nact = min(ITERS, (len + TILE - 1) / TILE);  // active tiles

    // 32-bit element offsets (max index 8.4M << 2^31): no IMAD.WIDE chains
    const int tbase = b * (T * V4D) + s * SLICE_V4 + l + q * (RPT * V4D);
    const float4* xptr = reinterpret_cast<const float4*>(x) + tbase;
    float4*       optr = reinterpret_cast<float4*>(out) + tbase;

    float4 carry = make_float4(0.f, 0.f, 0.f, 0.f);

    // ================= Phase A: pipelined active tiles =================
    float4 cur[RPT];
    if (nact > 0) {
        #pragma unroll
        for (int i = 0; i < RPT; i++)
            cur[i] = __ldcs(xptr + i * V4D);
    }

    for (int it = 0; it < nact; it++) {
        const int pb = it & 1;
        const int r0 = it * TILE + q * RPT;
        const bool more = (it + 1 < nact);

        // ---- prefetch tile i+1 FIRST: full-iteration latency cover ----
        float4 nxt[RPT];
        if (more) {                                // block-uniform
            #pragma unroll
            for (int i = 0; i < RPT; i++)
                nxt[i] = __ldcs(xptr + (TILE_STRIDE + i * V4D));
        }

        // ---- Pass 1: gelu once, serial prefix; c stays in registers ----
        float4 c[RPT];
        float4 run = make_float4(0.f, 0.f, 0.f, 0.f);
        #pragma unroll
        for (int i = 0; i < RPT; i++) {
            c[i] = cur[i];
            if (r0 + i < len) {                    // warp-uniform
                run.x += gelu_exact(cur[i].x);
                run.y += gelu_exact(cur[i].y);
                run.z += gelu_exact(cur[i].z);
                run.w += gelu_exact(cur[i].w);
                c[i].x += run.x; c[i].y += run.y;
                c[i].z += run.z; c[i].w += run.w;
            }
        }

        part[pb][q * 5 + l] = run;
        __syncthreads();

        // ---- two-level scan: warp w scans half hh of column cw ----
        {
            const int idx = hh * 32 + lane;
            float4 v = part[pb][idx * 5 + cw];
            float4 inc = v;
            #pragma unroll
            for (int d = 1; d < 32; d <<= 1) {
                float nx = __shfl_up_sync(0xffffffffu, inc.x, d);
                float ny = __shfl_up_sync(0xffffffffu, inc.y, d);
                float nz = __shfl_up_sync(0xffffffffu, inc.z, d);
                float nw = __shfl_up_sync(0xffffffffu, inc.w, d);
                if (lane >= d) { inc.x += nx; inc.y += ny; inc.z += nz; inc.w += nw; }
            }
            float4 ex;
            ex.x = inc.x - v.x; ex.y = inc.y - v.y;
            ex.z = inc.z - v.z; ex.w = inc.w - v.w;
            part[pb][idx * 5 + cw] = ex;           // half-exclusive, in place
            if (lane == 31) htot[pb][hh][cw] = inc;   // half total
        }
        __syncthreads();

        // ---- Pass 2: out = c + valid*(carry + excl); advance carry ----
        float4 ex = part[pb][q * 5 + l];
        float4 lo = htot[pb][0][l];
        float4 hi = htot[pb][1][l];
        float4 off;
        off.x = carry.x + ex.x; off.y = carry.y + ex.y;
        off.z = carry.z + ex.z; off.w = carry.w + ex.w;
        if (q >= 32) {                             // warp-uniform: add lower-half total
            off.x += lo.x; off.y += lo.y; off.z += lo.z; off.w += lo.w;
        }
        carry.x += lo.x + hi.x; carry.y += lo.y + hi.y;
        carry.z += lo.z + hi.z; carry.w += lo.w + hi.w;

        #pragma unroll
        for (int i = 0; i < RPT; i++) {
            float4 o = c[i];
            if (r0 + i < len) {                    // warp-uniform
                o.x += off.x; o.y += off.y;
                o.z += off.z; o.w += off.w;
            }
            __stcs(optr + i * V4D, o);
        }

        xptr += TILE_STRIDE;
        optr += TILE_STRIDE;
        if (more) {
            #pragma unroll
            for (int i = 0; i < RPT; i++) cur[i] = nxt[i];
        }
        // no trailing barrier: next tile uses the other smem buffer
    }

    // ============ Phase B: masked tail = pure streaming copy ============
    for (int it = nact; it < ITERS; it++) {
        float4 v[RPT];
        #pragma unroll
        for (int i = 0; i < RPT; i++)
            v[i] = __ldcs(xptr + i * V4D);
        #pragma unroll
        for (int i = 0; i < RPT; i++)
            __stcs(optr + i * V4D, v[i]);
        xptr += TILE_STRIDE;
        optr += TILE_STRIDE;
    }
}

extern "C" void kernel_launch(void* const* d_in, const int* in_sizes, int n_in,
                              void* d_out, int out_size) {
    const float* x   = (const float*)d_in[0];
    const void*  len = (const void*)d_in[1];
    float*       out = (float*)d_out;

    fused_kernel<<<NCTAS, THREADS>>>(x, len, out);
}

// round 11
// speedup vs baseline: 1.1149x; 1.1149x over previous
#include <cuda_runtime.h>
#include <cstdint>

// Problem shape (fixed by the dataset)
#define B  8
#define T  4096
#define D  1024
#define V4D 256                     // float4 per row
#define SLICES 64                   // 16-float D-slices
#define SLICE_V4 4                  // 4 float4 per slice
#define TILE 256                    // rows per tile iteration
#define QN   64                     // row-blocks per tile (TILE/RPT)
#define RPT  4                      // rows per thread per tile
#define THREADS 256                 // 64 q-blocks x 4 columns
#define ITERS (T / TILE)            // 16
#define NCTAS (B * SLICES)          // 512  (single wave at 4 CTAs/SM)
#define TILE_STRIDE (TILE * V4D)    // float4 elements per tile step

// exact gelu via erff (polynomial path, no MUFU exp):
// jax.nn.gelu(approximate=False) = 0.5*x*(1+erf(x/sqrt(2)))
__device__ __forceinline__ float gelu_exact(float x) {
    return 0.5f * x * (1.0f + erff(x * 0.7071067811865476f));
}

// lengths dtype sniffing: reference asks for int64 but JAX default config
// (x64 disabled) emits int32. Reading the first 8 int32 words is safe under
// BOTH layouts. If genuine int64, every odd 32-bit word is the zero
// high-half (lengths < 4096). If int32, odd words are random lengths.
__device__ __forceinline__ int load_length(const void* lp, int b) {
    const int* p32 = (const int*)lp;
    bool is64 = (p32[1] == 0) & (p32[3] == 0) & (p32[5] == 0) & (p32[7] == 0);
    if (is64) return (int)((const long long*)lp)[b];
    return p32[b];
}

__global__ void __launch_bounds__(THREADS, 4)
fused_kernel(const float* __restrict__ x,
             const void* __restrict__ lengths,
             float* __restrict__ out) {
    // only scan state in smem (c stays in registers), double-buffered
    __shared__ float4 part[2][QN * 5];            // stride 5: conflict-free
    __shared__ float4 htot[2][2][SLICE_V4];       // half-column totals

    const int tid  = threadIdx.x;
    const int q    = tid >> 2;      // row-block index  [0,64)
    const int l    = tid & 3;       // float4 column    [0,4)
    const int lane = tid & 31;
    const int w    = tid >> 5;      // warp id [0,8)
    const int cw   = w & 3;         // scan column of this warp
    const int hh   = w >> 2;        // scan half of this warp

    const int s = blockIdx.x & (SLICES - 1);
    const int b = blockIdx.x >> 6;
    const int len = load_length(lengths, b);
    const int nact = min(ITERS, (len + TILE - 1) / TILE);  // active tiles

    // 32-bit element offsets (max index 8.4M << 2^31): no IMAD.WIDE chains
    const int tbase = b * (T * V4D) + s * SLICE_V4 + l + q * (RPT * V4D);
    const float4* xptr = reinterpret_cast<const float4*>(x) + tbase;
    float4*       optr = reinterpret_cast<float4*>(out) + tbase;

    float4 carry = make_float4(0.f, 0.f, 0.f, 0.f);

    // ================= Phase A: pipelined active tiles =================
    float4 cur[RPT];
    if (nact > 0) {
        #pragma unroll
        for (int i = 0; i < RPT; i++)
            cur[i] = __ldcs(xptr + i * V4D);
    }

    for (int it = 0; it < nact; it++) {
        const int pb = it & 1;
        const int r0 = it * TILE + q * RPT;

        // ---- Pass 1: gelu consumes cur into c (registers only) ----
        float4 c[RPT];
        float4 run = make_float4(0.f, 0.f, 0.f, 0.f);
        #pragma unroll
        for (int i = 0; i < RPT; i++) {
            c[i] = cur[i];
            if (r0 + i < len) {                    // warp-uniform
                run.x += gelu_exact(cur[i].x);
                run.y += gelu_exact(cur[i].y);
                run.z += gelu_exact(cur[i].z);
                run.w += gelu_exact(cur[i].w);
                c[i].x += run.x; c[i].y += run.y;
                c[i].z += run.z; c[i].w += run.w;
            }
        }

        // ---- prefetch next tile into cur (now dead): covers scan+stores ----
        if (it + 1 < nact) {                       // block-uniform
            #pragma unroll
            for (int i = 0; i < RPT; i++)
                cur[i] = __ldcs(xptr + (TILE_STRIDE + i * V4D));
        }

        part[pb][q * 5 + l] = run;
        __syncthreads();

        // ---- two-level scan: warp w scans half hh of column cw ----
        {
            const int idx = hh * 32 + lane;
            float4 v = part[pb][idx * 5 + cw];
            float4 inc = v;
            #pragma unroll
            for (int d = 1; d < 32; d <<= 1) {
                float nx = __shfl_up_sync(0xffffffffu, inc.x, d);
                float ny = __shfl_up_sync(0xffffffffu, inc.y, d);
                float nz = __shfl_up_sync(0xffffffffu, inc.z, d);
                float nw = __shfl_up_sync(0xffffffffu, inc.w, d);
                if (lane >= d) { inc.x += nx; inc.y += ny; inc.z += nz; inc.w += nw; }
            }
            float4 ex;
            ex.x = inc.x - v.x; ex.y = inc.y - v.y;
            ex.z = inc.z - v.z; ex.w = inc.w - v.w;
            part[pb][idx * 5 + cw] = ex;           // half-exclusive, in place
            if (lane == 31) htot[pb][hh][cw] = inc;   // half total
        }
        __syncthreads();

        // ---- Pass 2: out = c + valid*(carry + excl); advance carry ----
        float4 ex = part[pb][q * 5 + l];
        float4 lo = htot[pb][0][l];
        float4 hi = htot[pb][1][l];
        float4 off;
        off.x = carry.x + ex.x; off.y = carry.y + ex.y;
        off.z = carry.z + ex.z; off.w = carry.w + ex.w;
        if (q >= 32) {                             // warp-uniform: add lower-half total
            off.x += lo.x; off.y += lo.y; off.z += lo.z; off.w += lo.w;
        }
        carry.x += lo.x + hi.x; carry.y += lo.y + hi.y;
        carry.z += lo.z + hi.z; carry.w += lo.w + hi.w;

        #pragma unroll
        for (int i = 0; i < RPT; i++) {
            float4 o = c[i];
            if (r0 + i < len) {                    // warp-uniform
                o.x += off.x; o.y += off.y;
                o.z += off.z; o.w += off.w;
            }
            __stcs(optr + i * V4D, o);
        }

        xptr += TILE_STRIDE;
        optr += TILE_STRIDE;
        // no trailing barrier: next tile uses the other smem buffer
    }

    // ============ Phase B: masked tail = pure streaming copy ============
    for (int it = nact; it < ITERS; it++) {
        float4 v[RPT];
        #pragma unroll
        for (int i = 0; i < RPT; i++)
            v[i] = __ldcs(xptr + i * V4D);
        #pragma unroll
        for (int i = 0; i < RPT; i++)
            __stcs(optr + i * V4D, v[i]);
        xptr += TILE_STRIDE;
        optr += TILE_STRIDE;
    }
}

extern "C" void kernel_launch(void* const* d_in, const int* in_sizes, int n_in,
                              void* d_out, int out_size) {
    const float* x   = (const float*)d_in[0];
    const void*  len = (const void*)d_in[1];
    float*       out = (float*)d_out;

    fused_kernel<<<NCTAS, THREADS>>>(x, len, out);
}